// round 3
// baseline (speedup 1.0000x reference)
#include <cuda_runtime.h>
#include <cuda_fp16.h>
#include <cstdint>

#define DEV_INLINE __device__ __forceinline__

// ---------------- problem sizes ----------------
static constexpr int kB = 16384;
static constexpr int kD = 1024;
static constexpr int kU = 128;

// ---------------- tiling ----------------
static constexpr int DCHUNK = 64;                 // features per K-chunk
static constexpr int NCHUNK = kD / DCHUNK;        // 16
static constexpr int TILES  = 6;                  // x + 5 rbf streams
static constexpr int TILE_HALVES = 128 * DCHUNK;  // 8192 fp16 per [128,64] tile
static constexpr int TILE_BYTES  = TILE_HALVES * 2;  // 16384 B (128 rows x 128B, SW128)
static constexpr int W_HALVES = NCHUNK * TILES * TILE_HALVES;  // 786432

// smem layout (dynamic): A streams then B streams, both SW128-swizzled
static constexpr int SMEM_A_OFF = 0;
static constexpr int SMEM_B_OFF = SMEM_A_OFF + TILES * TILE_BYTES;   // 98304
static constexpr int SMEM_TOTAL = SMEM_B_OFF + TILES * TILE_BYTES;   // 196608

// prepacked, pre-swizzled fp16 weights: [chunk][tile][128 rows(N=U)][64 cols(K)] SW128
__device__ __half g_Wpack[W_HALVES];

// ---------------- PTX helpers ----------------
DEV_INLINE uint32_t smem_u32(const void* p) {
    uint32_t a;
    asm("{ .reg .u64 t; cvta.to.shared.u64 t, %1; cvt.u32.u64 %0, t; }" : "=r"(a) : "l"(p));
    return a;
}

#define LDSM_X4(r, addr)                                                        \
    asm volatile("ldmatrix.sync.aligned.m8n8.x4.shared.b16 {%0,%1,%2,%3}, [%4];"\
                 : "=r"((r)[0]), "=r"((r)[1]), "=r"((r)[2]), "=r"((r)[3])       \
                 : "r"(addr))

DEV_INLINE void mma16816(float* d, const uint32_t* a, uint32_t b0, uint32_t b1) {
    asm volatile(
        "mma.sync.aligned.m16n8k16.row.col.f32.f16.f16.f32 "
        "{%0,%1,%2,%3}, {%4,%5,%6,%7}, {%8,%9}, {%0,%1,%2,%3};"
        : "+f"(d[0]), "+f"(d[1]), "+f"(d[2]), "+f"(d[3])
        : "r"(a[0]), "r"(a[1]), "r"(a[2]), "r"(a[3]), "r"(b0), "r"(b1));
}

// ---------------- weight prep: fp32 -> fp16, tiled + SW128 swizzled ----------------
__global__ void kan_prep_weights(const float* __restrict__ bw,
                                 const float* __restrict__ sw) {
    int idx = blockIdx.x * blockDim.x + threadIdx.x;
    if (idx >= W_HALVES) return;
    int k  = idx & (DCHUNK - 1);      // K within chunk (feature within chunk)
    int n  = (idx >> 6) & 127;        // N = output unit u
    int ct = idx >> 13;               // chunk*6 + tile
    int t  = ct % TILES;
    int c  = ct / TILES;
    int i  = c * DCHUNK + k;          // feature index
    float v = (t == 0) ? bw[i * kU + n]
                       : sw[(size_t)(i * kU + n) * 8 + (t - 1)];
    unsigned off = (unsigned)(n * 128 + k * 2);
    unsigned swz = off ^ ((off >> 3) & 0x70);
    g_Wpack[(size_t)ct * TILE_HALVES + (swz >> 1)] = __float2half(v);
}

// ---------------- main fused kernel (warp-level HMMA) ----------------
__global__ void __launch_bounds__(512, 1)
kan_main_kernel(const float* __restrict__ x, float* __restrict__ out) {
    extern __shared__ char smem[];
    const uint32_t smem_base = smem_u32(smem);
    const int tid  = threadIdx.x;
    const int wid  = tid >> 5;
    const int lane = tid & 31;

    // warp -> (mi, ni) subtile of the 128x128 CTA tile; each warp owns 32x32
    const int mi = wid & 3;
    const int ni = wid >> 2;

    const int row_base = blockIdx.x * 128;

    // accumulators: [mb(0..1)][nb(0..3)][4 regs], base and spline
    float acc0[2][4][4];
    float acc1[2][4][4];
    #pragma unroll
    for (int b = 0; b < 2; ++b)
        #pragma unroll
        for (int n = 0; n < 4; ++n)
            #pragma unroll
            for (int j = 0; j < 4; ++j) { acc0[b][n][j] = 0.f; acc1[b][n][j] = 0.f; }

    // -------- per-lane ldmatrix address components --------
    // A x4 (per m16 block b): lanes 0-7 rows +0..7 @k0, 8-15 rows +8..15 @k0,
    //                         16-23 rows +0..7 @k+16B, 24-31 rows +8..15 @k+16B
    const int aRowLocal = (lane & 7) + ((lane >> 3) & 1) * 8;  // within m16
    const uint32_t kbA_hi = ((lane >> 4) & 1) * 16;            // +16B for lanes 16-31
    uint32_t aRowOff[2], aXor[2];
    #pragma unroll
    for (int b = 0; b < 2; ++b) {
        int r = mi * 32 + b * 16 + aRowLocal;
        aRowOff[b] = (uint32_t)(r * 128);
        aXor[b]    = (uint32_t)((r & 7) << 4);
    }
    // B x4: lanes 0..31 -> rows ni*32 + lane (reg j <- lanes 8j..8j+7 = n-block j)
    const int rB = ni * 32 + lane;
    const uint32_t bRowOff = (uint32_t)(rB * 128);
    const uint32_t bXor    = (uint32_t)((rB & 7) << 4);

    const uint32_t aBase = smem_base + SMEM_A_OFF;
    const uint32_t bBase = smem_base + SMEM_B_OFF;

    const float C5   = 6.737946999085467e-3f;  // exp(-5)
    const float C125 = 0.2865047968601901f;    // exp(-1.25)

    for (int c = 0; c < NCHUNK; ++c) {
        if (c > 0) __syncthreads();  // previous consume done before overwriting smem

        // ---- B tiles: vectorized copy of pre-swizzled weights ----
        {
            const uint4* wsrc = reinterpret_cast<const uint4*>(g_Wpack) +
                                (size_t)c * (TILES * TILE_BYTES / 16);
            uint4* wdst = reinterpret_cast<uint4*>(smem + SMEM_B_OFF);
            #pragma unroll
            for (int j = 0; j < (TILES * TILE_BYTES / 16) / 512; ++j)
                wdst[tid + j * 512] = wsrc[tid + j * 512];
        }

        // ---- A tiles: load x, compute rbf (3 MUFU/elem), store fp16 swizzled ----
        {
            const int i0 = c * DCHUNK;
            #pragma unroll
            for (int it = 0; it < 8; ++it) {
                int e  = tid + it * 512;          // 0..4095 element-pairs
                int r  = e >> 5;                  // row within tile
                int kp = e & 31;                  // half2 column
                float2 xv = *reinterpret_cast<const float2*>(
                    x + (size_t)(row_base + r) * kD + i0 + kp * 2);

                float x0 = xv.x, x1 = xv.y;
                float s0 = __expf(-5.f * x0 * x0), s1 = __expf(-5.f * x1 * x1);
                float t0 = __expf(5.f * x0),       t1 = __expf(5.f * x1);
                float u0 = __expf(-5.f * x0),      u1 = __expf(-5.f * x1);

                __half2 hx = __floats2half2_rn(x0, x1);
                __half2 h0 = __floats2half2_rn(s0 * u0 * u0 * C5,  s1 * u1 * u1 * C5);  // c=-1
                __half2 h1 = __floats2half2_rn(s0 * u0 * C125,     s1 * u1 * C125);     // c=-0.5
                __half2 h2 = __floats2half2_rn(s0,                 s1);                 // c=0
                __half2 h3 = __floats2half2_rn(s0 * t0 * C125,     s1 * t1 * C125);     // c=0.5
                __half2 h4 = __floats2half2_rn(s0 * t0 * t0 * C5,  s1 * t1 * t1 * C5);  // c=1

                unsigned off = (unsigned)(r * 128 + kp * 4);
                unsigned swz = off ^ ((off >> 3) & 0x70);
                char* ab = smem + SMEM_A_OFF + swz;
                *reinterpret_cast<__half2*>(ab + 0 * TILE_BYTES) = hx;
                *reinterpret_cast<__half2*>(ab + 1 * TILE_BYTES) = h0;
                *reinterpret_cast<__half2*>(ab + 2 * TILE_BYTES) = h1;
                *reinterpret_cast<__half2*>(ab + 3 * TILE_BYTES) = h2;
                *reinterpret_cast<__half2*>(ab + 4 * TILE_BYTES) = h3;
                *reinterpret_cast<__half2*>(ab + 5 * TILE_BYTES) = h4;
            }
        }

        __syncthreads();

        // ---- consume: 4 k16-steps x 6 streams; stream 0 -> acc0, 1..5 -> acc1 ----
        #pragma unroll
        for (int q = 0; q < 4; ++q) {
            #pragma unroll
            for (int s = 0; s < TILES; ++s) {
                const uint32_t sOff = (uint32_t)(s * TILE_BYTES);

                uint32_t a[8];
                #pragma unroll
                for (int b = 0; b < 2; ++b) {
                    uint32_t kb = (uint32_t)(q * 32) + kbA_hi;
                    uint32_t addr = aBase + sOff + aRowOff[b] + (kb ^ aXor[b]);
                    LDSM_X4(a + b * 4, addr);
                }
                uint32_t bb[8];  // bb[h*4+j]: n-block j, k-half h
                #pragma unroll
                for (int h = 0; h < 2; ++h) {
                    uint32_t kb = (uint32_t)(q * 32 + h * 16);
                    uint32_t addr = bBase + sOff + bRowOff + (kb ^ bXor);
                    LDSM_X4(bb + h * 4, addr);
                }

                if (s == 0) {
                    #pragma unroll
                    for (int b = 0; b < 2; ++b)
                        #pragma unroll
                        for (int nb = 0; nb < 4; ++nb)
                            mma16816(acc0[b][nb], a + b * 4, bb[nb], bb[4 + nb]);
                } else {
                    #pragma unroll
                    for (int b = 0; b < 2; ++b)
                        #pragma unroll
                        for (int nb = 0; nb < 4; ++nb)
                            mma16816(acc1[b][nb], a + b * 4, bb[nb], bb[4 + nb]);
                }
            }
        }
    }

    // ---- epilogue: SiLU(base) + spline, float2 stores ----
    {
        const int colBase = ni * 32 + (lane & 3) * 2;
        #pragma unroll
        for (int b = 0; b < 2; ++b) {
            int row0 = row_base + mi * 32 + b * 16 + (lane >> 2);
            #pragma unroll
            for (int nb = 0; nb < 4; ++nb) {
                int col = colBase + nb * 8;
                float z0 = acc0[b][nb][0], z1 = acc0[b][nb][1];
                float z2 = acc0[b][nb][2], z3 = acc0[b][nb][3];
                float2 v0, v1;
                v0.x = __fdividef(z0, 1.f + __expf(-z0)) + acc1[b][nb][0];
                v0.y = __fdividef(z1, 1.f + __expf(-z1)) + acc1[b][nb][1];
                v1.x = __fdividef(z2, 1.f + __expf(-z2)) + acc1[b][nb][2];
                v1.y = __fdividef(z3, 1.f + __expf(-z3)) + acc1[b][nb][3];
                *reinterpret_cast<float2*>(out + (size_t)row0 * kU + col)       = v0;
                *reinterpret_cast<float2*>(out + (size_t)(row0 + 8) * kU + col) = v1;
            }
        }
    }
}

// ---------------- launch ----------------
extern "C" void kernel_launch(void* const* d_in, const int* in_sizes, int n_in,
                              void* d_out, int out_size) {
    (void)in_sizes; (void)n_in; (void)out_size;
    const float* x  = (const float*)d_in[0];
    const float* bw = (const float*)d_in[1];
    const float* sw = (const float*)d_in[2];
    float* out = (float*)d_out;

    cudaFuncSetAttribute(kan_main_kernel,
                         cudaFuncAttributeMaxDynamicSharedMemorySize, SMEM_TOTAL);

    kan_prep_weights<<<(W_HALVES + 255) / 256, 256>>>(bw, sw);
    kan_main_kernel<<<kB / 128, 512, SMEM_TOTAL>>>(x, out);
}